// round 15
// baseline (speedup 1.0000x reference)
#include <cuda_runtime.h>
#include <cuda_fp16.h>
#include <math_constants.h>

// Problem constants (fixed by the dataset shapes)
#define B_  2
#define H_  50
#define W_  50
#define C_  256
#define R_  100
#define PH 7
#define PW 7

#define NPOS        (B_ * H_ * W_)   // 5000 spatial positions
#define VEC_PER_POS (C_ / 8)         // 32 uint4 (8 fp16) per position
#define NVEC        (NPOS * VEC_PER_POS)

// fp16 copy of the feature map (scratch: 2.56 MB, static __device__ per rules)
__device__ uint4 g_fm16[NVEC];

// ---------------------------------------------------------------------------
// Pass 1: f32 -> fp16 conversion (5 MB read, 2.5 MB write)
// ---------------------------------------------------------------------------
__global__ void __launch_bounds__(256) convert_kernel(const float* __restrict__ fm)
{
    const int i = blockIdx.x * blockDim.x + threadIdx.x;   // uint4 index
    const float4* __restrict__ src = reinterpret_cast<const float4*>(fm) + (size_t)i * 2;
    float4 a = __ldg(src + 0);
    float4 b = __ldg(src + 1);
    __half2 h0 = __floats2half2_rn(a.x, a.y);
    __half2 h1 = __floats2half2_rn(a.z, a.w);
    __half2 h2 = __floats2half2_rn(b.x, b.y);
    __half2 h3 = __floats2half2_rn(b.z, b.w);
    uint4 v;
    v.x = *reinterpret_cast<unsigned int*>(&h0);
    v.y = *reinterpret_cast<unsigned int*>(&h1);
    v.z = *reinterpret_cast<unsigned int*>(&h2);
    v.w = *reinterpret_cast<unsigned int*>(&h3);
    g_fm16[i] = v;
}

// ---------------------------------------------------------------------------
// Pass 2: ROI max-pool on fp16 data.
// One block per (b, roi, row_bin); block = (32 lanes x 7 col-bins) = 224 thr.
// Each lane covers 8 channels (one 16B load per position). 9 blocks/SM
// resident -> ~98% occupancy, ~1 wave.
// ---------------------------------------------------------------------------
__global__ void __launch_bounds__(32 * PW, 9) roi_pool_kernel(
    const float* __restrict__ rois,   // (B, R, 4)
    float* __restrict__ out)          // (B, R, PH, PW, C)
{
    const int blk  = blockIdx.x;
    const int bi   = blk % PH;                 // row bin
    const int r    = (blk / PH) % R_;
    const int b    = blk / (PH * R_);
    const int lane = threadIdx.x;              // 8-channel group
    const int j    = threadIdx.y;              // column bin

    const float4 roi = *reinterpret_cast<const float4*>(rois + (size_t)(b * R_ + r) * 4);

    // Mirror reference: truncating cast of f32 products (all coords >= 0)
    const int hs = (int)(H_ * roi.x);
    const int ws = (int)(W_ * roi.y);
    const int he = (int)(H_ * roi.z);
    const int we = (int)(W_ * roi.w);

    const int sh = max((he - hs) / PH, 1);
    const int sw = max((we - ws) / PW, 1);

    // Row/col range for this bin. Last bin absorbs the remainder.
    const int y0 = hs + bi * sh;
    const int y1 = (bi == PH - 1) ? he : min(hs + (bi + 1) * sh, he);
    const int x0 = ws + j * sw;
    const int x1 = (j == PW - 1) ? we : min(ws + (j + 1) * sw, we);

    const uint4* __restrict__ base =
        g_fm16 + ((size_t)b * H_ * W_) * VEC_PER_POS + lane;

    const __half  ninf_h = __ushort_as_half((unsigned short)0xFC00);
    const __half2 NINF2  = __halves2half2(ninf_h, ninf_h);
    __half2 a0 = NINF2, a1 = NINF2, a2 = NINF2, a3 = NINF2;   // chain A
    __half2 b0 = NINF2, b1 = NINF2, b2 = NINF2, b3 = NINF2;   // chain B

    for (int y = y0; y < y1; ++y) {
        const uint4* __restrict__ row = base + ((size_t)y * W_ + x0) * VEC_PER_POS;
        int x = x0;
        // 2-way x-unroll: two independent 16B loads + hmax2 chains in flight
        for (; x + 1 < x1; x += 2) {
            uint4 v0 = __ldg(row);
            uint4 v1 = __ldg(row + VEC_PER_POS);
            row += 2 * VEC_PER_POS;
            a0 = __hmax2(a0, *reinterpret_cast<__half2*>(&v0.x));
            a1 = __hmax2(a1, *reinterpret_cast<__half2*>(&v0.y));
            a2 = __hmax2(a2, *reinterpret_cast<__half2*>(&v0.z));
            a3 = __hmax2(a3, *reinterpret_cast<__half2*>(&v0.w));
            b0 = __hmax2(b0, *reinterpret_cast<__half2*>(&v1.x));
            b1 = __hmax2(b1, *reinterpret_cast<__half2*>(&v1.y));
            b2 = __hmax2(b2, *reinterpret_cast<__half2*>(&v1.z));
            b3 = __hmax2(b3, *reinterpret_cast<__half2*>(&v1.w));
        }
        if (x < x1) {
            uint4 v0 = __ldg(row);
            a0 = __hmax2(a0, *reinterpret_cast<__half2*>(&v0.x));
            a1 = __hmax2(a1, *reinterpret_cast<__half2*>(&v0.y));
            a2 = __hmax2(a2, *reinterpret_cast<__half2*>(&v0.z));
            a3 = __hmax2(a3, *reinterpret_cast<__half2*>(&v0.w));
        }
    }
    a0 = __hmax2(a0, b0);
    a1 = __hmax2(a1, b1);
    a2 = __hmax2(a2, b2);
    a3 = __hmax2(a3, b3);

    // Convert back to f32 and store 8 channels (two float4 = 32B/thread;
    // warp writes 1KB contiguous).
    float2 f0 = __half22float2(a0);
    float2 f1 = __half22float2(a1);
    float2 f2 = __half22float2(a2);
    float2 f3 = __half22float2(a3);

    float4* __restrict__ o = reinterpret_cast<float4*>(
        out + ((((size_t)(b * R_ + r)) * PH + bi) * PW + j) * C_ + lane * 8);
    o[0] = make_float4(f0.x, f0.y, f1.x, f1.y);
    o[1] = make_float4(f2.x, f2.y, f3.x, f3.y);
}

extern "C" void kernel_launch(void* const* d_in, const int* in_sizes, int n_in,
                              void* d_out, int out_size)
{
    const float* fm   = (const float*)d_in[0];   // feature_map (2,50,50,256)
    const float* rois = (const float*)d_in[1];   // rois (2,100,4)
    float* out = (float*)d_out;                  // (2,100,7,7,256)

    (void)in_sizes; (void)n_in; (void)out_size;

    // Pass 1: 160000 uint4 outputs / 256 threads = 625 blocks (exact)
    convert_kernel<<<NVEC / 256, 256>>>(fm);

    // Pass 2
    dim3 grid(B_ * R_ * PH);
    dim3 block(32, PW);
    roi_pool_kernel<<<grid, block>>>(rois, out);
}

// round 16
// speedup vs baseline: 1.2353x; 1.2353x over previous
#include <cuda_runtime.h>
#include <math_constants.h>

// Problem constants (fixed by the dataset shapes)
#define B_  2
#define H_  50
#define W_  50
#define C_  256
#define R_  100
#define PH 7
#define PW 7
#define C4V 64            // float4 per spatial position (256 ch / 4)

__device__ __forceinline__ float4 fmax4(float4 a, float4 b) {
    return make_float4(fmaxf(a.x, b.x), fmaxf(a.y, b.y),
                       fmaxf(a.z, b.z), fmaxf(a.w, b.w));
}

// One block per (b, roi, row_bin). Block = (32 lanes x 8 warps).
// Warps 0..6 own column bins 0..6; warp 7 takes the UPPER HALF of bin 6's
// columns (the only bin that absorbs the division remainder) and merges
// with warp 6 through smem — halves the corner-bin critical path that
// bounds the single-wave makespan. Each lane covers 8 channels.
__global__ void __launch_bounds__(256) roi_pool_kernel(
    const float* __restrict__ fm,     // (B, H, W, C)
    const float* __restrict__ rois,   // (B, R, 4)
    float* __restrict__ out)          // (B, R, PH, PW, C)
{
    const int blk  = blockIdx.x;
    const int bi   = blk % PH;                 // row bin
    const int r    = (blk / PH) % R_;
    const int b    = blk / (PH * R_);
    const int lane = threadIdx.x;              // 8-channel group
    const int warp = threadIdx.y;              // 0..7

    const float4 roi = *reinterpret_cast<const float4*>(rois + (size_t)(b * R_ + r) * 4);

    // Mirror reference: truncating cast of f32 products (all coords >= 0)
    const int hs = (int)(H_ * roi.x);
    const int ws = (int)(W_ * roi.y);
    const int he = (int)(H_ * roi.z);
    const int we = (int)(W_ * roi.w);

    const int sh = max((he - hs) / PH, 1);
    const int sw = max((we - ws) / PW, 1);

    // Row range for this row-bin. Last bin absorbs the remainder.
    const int y0 = hs + bi * sh;
    const int y1 = (bi == PH - 1) ? he : min(hs + (bi + 1) * sh, he);

    // Column range: warps 0..5 = bins 0..5 (exact width sw);
    // bin 6 = [ws+6*sw, we) split between warp 6 (lower half) and warp 7 (upper).
    const int j = (warp < 7) ? warp : 6;       // bin this warp contributes to
    int x0, x1;
    if (warp < 6) {
        x0 = ws + warp * sw;
        x1 = min(x0 + sw, we);
    } else {
        const int x6 = ws + 6 * sw;
        const int w6 = we - x6;                // >= 1
        const int half = (w6 + 1) >> 1;
        if (warp == 6) { x0 = x6;        x1 = x6 + half; }
        else           { x0 = x6 + half; x1 = we;        }
    }

    const float4* __restrict__ fmb =
        reinterpret_cast<const float4*>(fm + (size_t)b * H_ * W_ * C_) + lane * 2;

    const float4 NEG_INF4 = make_float4(-CUDART_INF_F, -CUDART_INF_F,
                                        -CUDART_INF_F, -CUDART_INF_F);
    // Two positions in flight, two float4 each -> 4 independent load chains.
    float4 aL = NEG_INF4, aH = NEG_INF4;
    float4 bL = NEG_INF4, bH = NEG_INF4;

    for (int y = y0; y < y1; ++y) {
        const float4* __restrict__ p =
            fmb + ((size_t)y * W_ + x0) * C4V;
        int x = x0;
        for (; x + 1 < x1; x += 2, p += 2 * C4V) {
            float4 v0L = __ldg(p);
            float4 v0H = __ldg(p + 1);
            float4 v1L = __ldg(p + C4V);
            float4 v1H = __ldg(p + C4V + 1);
            aL = fmax4(aL, v0L);
            aH = fmax4(aH, v0H);
            bL = fmax4(bL, v1L);
            bH = fmax4(bH, v1H);
        }
        if (x < x1) {
            float4 v0L = __ldg(p);
            float4 v0H = __ldg(p + 1);
            aL = fmax4(aL, v0L);
            aH = fmax4(aH, v0H);
        }
    }
    aL = fmax4(aL, bL);
    aH = fmax4(aH, bH);

    // Warp 7 hands its partial to warp 6 through smem.
    __shared__ float4 s_part[32][2];
    if (warp == 7) {
        s_part[lane][0] = aL;
        s_part[lane][1] = aH;
    }
    __syncthreads();
    if (warp == 6) {
        aL = fmax4(aL, s_part[lane][0]);
        aH = fmax4(aH, s_part[lane][1]);
    }

    if (warp < 7) {
        float4* __restrict__ o = reinterpret_cast<float4*>(
            out + ((((size_t)(b * R_ + r)) * PH + bi) * PW + j) * C_ + lane * 8);
        o[0] = aL;
        o[1] = aH;
    }
}

extern "C" void kernel_launch(void* const* d_in, const int* in_sizes, int n_in,
                              void* d_out, int out_size)
{
    const float* fm   = (const float*)d_in[0];   // feature_map (2,50,50,256)
    const float* rois = (const float*)d_in[1];   // rois (2,100,4)
    float* out = (float*)d_out;                  // (2,100,7,7,256)

    (void)in_sizes; (void)n_in; (void)out_size;

    dim3 grid(B_ * R_ * PH);
    dim3 block(32, 8);
    roi_pool_kernel<<<grid, block>>>(fm, rois, out);
}